// round 1
// baseline (speedup 1.0000x reference)
#include <cuda_runtime.h>
#include <cstdint>

typedef unsigned long long ull;

#define SEQ   512
#define BATCH 64
#define DIN   256
#define HID   1024
#define SBH   (SEQ*BATCH*HID)

// ---------------- device state (no allocs allowed) ----------------
__device__ float g_h[2][BATCH*HID];      // ping-pong hidden state (512 KB, L2-resident)
__device__ unsigned g_bar_cnt;           // grid barrier counter (ends at 0 every launch)
__device__ unsigned g_bar_gen;           // grid barrier generation (monotonic, wrap-safe)

// ---------------- f32x2 packed-math helpers ----------------
__device__ __forceinline__ ull ffma2(ull a, ull b, ull c) {
    ull d;
    asm("fma.rn.f32x2 %0, %1, %2, %3;" : "=l"(d) : "l"(a), "l"(b), "l"(c));
    return d;
}
__device__ __forceinline__ ull pk2(float x, float y) {
    ull r; asm("mov.b64 %0, {%1, %2};" : "=l"(r) : "f"(x), "f"(y)); return r;
}
__device__ __forceinline__ float2 upk(ull v) {
    float2 r; asm("mov.b64 {%0, %1}, %2;" : "=f"(r.x), "=f"(r.y) : "l"(v)); return r;
}

// ---------------- init: h0 = 0 ----------------
__global__ void init_kernel() {
    int i = blockIdx.x * blockDim.x + threadIdx.x;
    if (i < BATCH*HID) g_h[0][i] = 0.0f;
}

// ---------------- phase 1: xp = x @ W_in^T + bias  (written into d_out) ----------------
// M = SEQ*BATCH = 32768, N = HID = 1024, K = DIN = 256
#define P1_BM 128
#define P1_BN 64
#define P1_BK 16

__global__ __launch_bounds__(256) void xproj_kernel(
        const float* __restrict__ x, const float* __restrict__ Win,
        const float* __restrict__ bias, float* __restrict__ out) {
    __shared__ ull As[P1_BM][9];   // [m][kp], 8 kpairs + 1 pad (conflict-free: stride 18 words)
    __shared__ ull Bs[P1_BN][9];

    const int t  = threadIdx.x;
    const int m0 = blockIdx.y * P1_BM;
    const int n0 = blockIdx.x * P1_BN;
    const int tm = t >> 4;         // 0..15  -> m = tm + 16*i
    const int tn = t & 15;         // 0..15  -> n = tn + 16*j

    ull acc[8][4];
    #pragma unroll
    for (int i = 0; i < 8; i++)
        #pragma unroll
        for (int j = 0; j < 4; j++) acc[i][j] = 0ull;

    for (int k0 = 0; k0 < DIN; k0 += P1_BK) {
        // A tile: 128 rows x 16 k = 512 float4, 2 per thread (coalesced)
        #pragma unroll
        for (int l = 0; l < 2; l++) {
            int idx = t + l * 256;
            int r = idx >> 2, c = idx & 3;
            float4 v = *reinterpret_cast<const float4*>(x + (size_t)(m0 + r) * DIN + k0 + c * 4);
            As[r][c*2]   = pk2(v.x, v.y);
            As[r][c*2+1] = pk2(v.z, v.w);
        }
        // B tile: 64 x 16 = 256 float4, 1 per thread
        {
            int r = t >> 2, c = t & 3;
            float4 v = *reinterpret_cast<const float4*>(Win + (size_t)(n0 + r) * DIN + k0 + c * 4);
            Bs[r][c*2]   = pk2(v.x, v.y);
            Bs[r][c*2+1] = pk2(v.z, v.w);
        }
        __syncthreads();
        #pragma unroll
        for (int kp = 0; kp < 8; kp++) {
            ull a[8], b[4];
            #pragma unroll
            for (int i = 0; i < 8; i++) a[i] = As[tm + 16*i][kp];
            #pragma unroll
            for (int j = 0; j < 4; j++) b[j] = Bs[tn + 16*j][kp];
            #pragma unroll
            for (int i = 0; i < 8; i++)
                #pragma unroll
                for (int j = 0; j < 4; j++)
                    acc[i][j] = ffma2(a[i], b[j], acc[i][j]);
        }
        __syncthreads();
    }
    #pragma unroll
    for (int i = 0; i < 8; i++) {
        int m = m0 + tm + 16*i;
        #pragma unroll
        for (int j = 0; j < 4; j++) {
            int n = n0 + tn + 16*j;
            float2 s = upk(acc[i][j]);
            out[(size_t)m * HID + n] = s.x + s.y + bias[n];
        }
    }
}

// ---------------- phase 2: persistent recurrent kernel ----------------
#define NBLK   128        // 64 j-tiles x 2 b-tiles, all co-resident (1 block/SM)
#define JT     16         // hidden cols per block
#define BT     32         // batch rows per block
#define CHUNK  256        // k per staged chunk
#define HSP    264        // hs row stride (floats): 264*4B -> banks 8b%32, conflict-free
#define HS_SLOT (BT*HSP)  // floats per chunk slot
// dynamic smem: Ws2 (512*16 ull = 64KB) then hs (2 * HS_SLOT floats = 66KB) -> 133120 B
#define SMEM_BYTES (512*16*8 + 2*HS_SLOT*4)

__device__ __forceinline__ void grid_barrier() {
    __syncthreads();
    if (threadIdx.x == 0) {
        __threadfence();
        unsigned gen = atomicAdd(&g_bar_gen, 0u);
        if (atomicAdd(&g_bar_cnt, 1u) == NBLK - 1) {
            atomicExch(&g_bar_cnt, 0u);
            __threadfence();
            atomicAdd(&g_bar_gen, 1u);
        } else {
            while (atomicAdd(&g_bar_gen, 0u) == gen) { __nanosleep(32); }
        }
        __threadfence();
    }
    __syncthreads();
}

__device__ __forceinline__ void stage_chunk(float* hs, const float* src_rowbase, int c, int t) {
    float* dst = hs + (c & 1) * HS_SLOT;
    const float* src = src_rowbase + c * CHUNK;
    #pragma unroll
    for (int i = 0; i < 8; i++) {
        int idx = t + i * 256;
        int r  = idx >> 6;        // 0..31 batch row
        int c4 = idx & 63;        // float4 within 256-float chunk row
        unsigned sa = (unsigned)__cvta_generic_to_shared(dst + r * HSP + (c4 << 2));
        asm volatile("cp.async.cg.shared.global [%0], [%1], 16;"
                     :: "r"(sa), "l"(src + (size_t)r * HID + (c4 << 2)));
    }
    asm volatile("cp.async.commit_group;");
}

__global__ __launch_bounds__(256) void rnn_kernel(
        const float* __restrict__ Whh, const float* __restrict__ alpha,
        float* __restrict__ out, int write_hn) {
    extern __shared__ char smem_raw[];
    ull*   Ws2 = reinterpret_cast<ull*>(smem_raw);            // [kp(512)][jl(16)], packed pairs
    float* hs  = reinterpret_cast<float*>(smem_raw + 512*16*8);

    const int t   = threadIdx.x;
    const int jt  = blockIdx.x & 63;
    const int bt  = blockIdx.x >> 6;
    const int j0  = jt * JT;
    const int b0g = bt * BT;

    // Load W_hh slice once, transposed to kpair-major: Ws2[kp*16+jl] = {W[j0+jl][2kp], W[j0+jl][2kp+1]}
    #pragma unroll
    for (int l = 0; l < 32; l++) {
        int idx = t + l * 256;          // 0..8191
        int jl  = idx >> 9;             // 0..15
        int kp  = idx & 511;            // 0..511  (coalesced global reads along kp)
        float2 v = *reinterpret_cast<const float2*>(Whh + (size_t)(j0 + jl) * HID + 2 * kp);
        Ws2[kp * 16 + jl] = pk2(v.x, v.y);
    }

    const int jl  = t & 15;
    const int bg  = t >> 4;
    const int bl0 = 2 * bg, bl1 = 2 * bg + 1;
    const int jg  = j0 + jl;
    const int bg0 = b0g + bl0, bg1 = b0g + bl1;
    const float a = alpha[jg];

    __syncthreads();   // Ws2 ready (stores above + first barrier below would also cover; be explicit)
    grid_barrier();    // also guarantees init_kernel's zeros are visible grid-wide via L2

    for (int step = 0; step < SEQ; step++) {
        const float* hcur = g_h[step & 1];
        float*       hnxt = g_h[(step + 1) & 1];
        const float* hrow = hcur + (size_t)b0g * HID;

        stage_chunk(hs, hrow, 0, t);

        ull acc0 = 0ull, acc1 = 0ull;
        #pragma unroll
        for (int c = 0; c < 4; c++) {
            if (c < 3) stage_chunk(hs, hrow, c + 1, t);
            if (c < 3) asm volatile("cp.async.wait_group 1;");
            else       asm volatile("cp.async.wait_group 0;");
            __syncthreads();

            const float* h0p = hs + (c & 1) * HS_SLOT + bl0 * HSP;
            const float* h1p = hs + (c & 1) * HS_SLOT + bl1 * HSP;
            const ull*   wp  = Ws2 + (c * 128) * 16 + jl;   // kp base = c*CHUNK/2

            #pragma unroll 8
            for (int kk = 0; kk < CHUNK; kk += 4) {
                ulonglong2 H0 = *reinterpret_cast<const ulonglong2*>(h0p + kk);
                ulonglong2 H1 = *reinterpret_cast<const ulonglong2*>(h1p + kk);
                ull WA = wp[(kk >> 1) * 16];
                ull WB = wp[(kk >> 1) * 16 + 16];
                acc0 = ffma2(H0.x, WA, acc0);
                acc0 = ffma2(H0.y, WB, acc0);
                acc1 = ffma2(H1.x, WA, acc1);
                acc1 = ffma2(H1.y, WB, acc1);
            }
            __syncthreads();   // protect slot before it is re-staged
        }

        float2 s0 = upk(acc0), s1 = upk(acc1);
        float d0 = s0.x + s0.y, d1 = s1.x + s1.y;

        size_t ob = (size_t)step * BATCH * HID;
        size_t i0 = ob + (size_t)bg0 * HID + jg;
        size_t i1 = ob + (size_t)bg1 * HID + jg;
        float xp0 = out[i0];                       // xp_t (phase-1 output, element owned by this thread)
        float xp1 = out[i1];
        float hp0 = __ldcg(hcur + (size_t)bg0 * HID + jg);
        float hp1 = __ldcg(hcur + (size_t)bg1 * HID + jg);

        float ht0 = tanhf(xp0 + d0);
        float ht1 = tanhf(xp1 + d1);
        float hn0 = hp0 + a * (ht0 - hp0);         // (1-a)*hp + a*ht
        float hn1 = hp1 + a * (ht1 - hp1);

        hnxt[(size_t)bg0 * HID + jg] = hn0;
        hnxt[(size_t)bg1 * HID + jg] = hn1;
        out[i0] = hn0;                              // in-place: xp_t -> h_t
        out[i1] = hn1;
        if (write_hn && step == SEQ - 1) {
            out[(size_t)SBH + (size_t)bg0 * HID + jg] = hn0;
            out[(size_t)SBH + (size_t)bg1 * HID + jg] = hn1;
        }

        grid_barrier();
    }
}

// ---------------- launch ----------------
extern "C" void kernel_launch(void* const* d_in, const int* in_sizes, int n_in,
                              void* d_out, int out_size) {
    const float* x     = (const float*)d_in[0];   // [512,64,256]
    const float* W_in  = (const float*)d_in[1];   // [1024,256]
    const float* W_hh  = (const float*)d_in[2];   // [1024,1024]
    const float* bias  = (const float*)d_in[3];   // [1024]
    const float* alpha = (const float*)d_in[4];   // [1024]
    float* out = (float*)d_out;

    static int smem_set = 0;
    // idempotent host-side attribute set (not an allocation, not a stream op)
    cudaFuncSetAttribute(rnn_kernel, cudaFuncAttributeMaxDynamicSharedMemorySize, SMEM_BYTES);
    (void)smem_set;

    init_kernel<<<(BATCH*HID + 255) / 256, 256>>>();

    dim3 g1(HID / P1_BN, (SEQ * BATCH) / P1_BM);  // (16, 256)
    xproj_kernel<<<g1, 256>>>(x, W_in, bias, out);

    int write_hn = (out_size >= SBH + BATCH * HID) ? 1 : 0;
    rnn_kernel<<<NBLK, 256, SMEM_BYTES>>>(W_hh, alpha, out, write_hn);
}

// round 2
// speedup vs baseline: 1.7821x; 1.7821x over previous
#include <cuda_runtime.h>
#include <cstdint>

typedef unsigned long long ull;

#define SEQ   512
#define BATCH 64
#define DIN   256
#define HID   1024
#define SBH   (SEQ*BATCH*HID)

// ---------------- persistent-kernel geometry ----------------
#define NBLK 128          // 64 j-tiles x 2 batch-groups, 1 block/SM
#define GRP  64           // blocks per barrier group (independent halves)
#define BT   32           // batch rows per block
#define JT   16           // hidden cols per block
#define HSP  1028         // hs row stride (floats): 1028 % 32 == 4 -> 8 consecutive rows conflict-free
#define WSP  18           // Ws2 stride (ull) per k-pair: 16B-aligned rows, 4kp%32 spread
#define RSP  520          // reduction buffer stride (floats) per warp

#define OFF_MBAR 0
#define OFF_W    128
#define OFF_H    (OFF_W + 512*WSP*8)            // 128 + 73728
#define OFF_RED  (OFF_H + BT*HSP*4)             // + 131584
#define SMEM_BYTES (OFF_RED + 8*RSP*4)          // 222080 B total

// ---------------- device state ----------------
__device__ float g_h[2][BATCH*HID];   // ping-pong hidden state (L2-resident)
__device__ unsigned g_cnt[2];
__device__ unsigned g_gen[2];

// ---------------- f32x2 helpers ----------------
__device__ __forceinline__ ull ffma2(ull a, ull b, ull c) {
    ull d; asm("fma.rn.f32x2 %0, %1, %2, %3;" : "=l"(d) : "l"(a), "l"(b), "l"(c)); return d;
}
__device__ __forceinline__ ull pk2(float x, float y) {
    ull r; asm("mov.b64 %0, {%1, %2};" : "=l"(r) : "f"(x), "f"(y)); return r;
}
__device__ __forceinline__ float2 upk(ull v) {
    float2 r; asm("mov.b64 {%0, %1}, %2;" : "=f"(r.x), "=f"(r.y) : "l"(v)); return r;
}

// ---------------- init ----------------
__global__ void init_kernel() {
    int i = blockIdx.x * blockDim.x + threadIdx.x;
    if (i < BATCH*HID) g_h[0][i] = 0.0f;
    if (i < 2) { g_cnt[i] = 0u; g_gen[i] = 0u; }
}

// ---------------- phase 1: xp = x @ W_in^T + bias (into d_out) ----------------
#define P1_BM 128
#define P1_BN 64
#define P1_BK 16

__global__ __launch_bounds__(256) void xproj_kernel(
        const float* __restrict__ x, const float* __restrict__ Win,
        const float* __restrict__ bias, float* __restrict__ out) {
    __shared__ ull As[P1_BM][9];
    __shared__ ull Bs[P1_BN][9];

    const int t  = threadIdx.x;
    const int m0 = blockIdx.y * P1_BM;
    const int n0 = blockIdx.x * P1_BN;
    const int tm = t >> 4;
    const int tn = t & 15;

    ull acc[8][4];
    #pragma unroll
    for (int i = 0; i < 8; i++)
        #pragma unroll
        for (int j = 0; j < 4; j++) acc[i][j] = 0ull;

    for (int k0 = 0; k0 < DIN; k0 += P1_BK) {
        #pragma unroll
        for (int l = 0; l < 2; l++) {
            int idx = t + l * 256;
            int r = idx >> 2, c = idx & 3;
            float4 v = *reinterpret_cast<const float4*>(x + (size_t)(m0 + r) * DIN + k0 + c * 4);
            As[r][c*2]   = pk2(v.x, v.y);
            As[r][c*2+1] = pk2(v.z, v.w);
        }
        {
            int r = t >> 2, c = t & 3;
            float4 v = *reinterpret_cast<const float4*>(Win + (size_t)(n0 + r) * DIN + k0 + c * 4);
            Bs[r][c*2]   = pk2(v.x, v.y);
            Bs[r][c*2+1] = pk2(v.z, v.w);
        }
        __syncthreads();
        #pragma unroll
        for (int kp = 0; kp < 8; kp++) {
            ull a[8], b[4];
            #pragma unroll
            for (int i = 0; i < 8; i++) a[i] = As[tm + 16*i][kp];
            #pragma unroll
            for (int j = 0; j < 4; j++) b[j] = Bs[tn + 16*j][kp];
            #pragma unroll
            for (int i = 0; i < 8; i++)
                #pragma unroll
                for (int j = 0; j < 4; j++)
                    acc[i][j] = ffma2(a[i], b[j], acc[i][j]);
        }
        __syncthreads();
    }
    #pragma unroll
    for (int i = 0; i < 8; i++) {
        int m = m0 + tm + 16*i;
        #pragma unroll
        for (int j = 0; j < 4; j++) {
            int n = n0 + tn + 16*j;
            float2 s = upk(acc[i][j]);
            out[(size_t)m * HID + n] = s.x + s.y + bias[n];
        }
    }
}

// ---------------- mbarrier / bulk copy helpers ----------------
__device__ __forceinline__ void mbar_wait(uint32_t mbar, uint32_t parity) {
    uint32_t done;
    do {
        asm volatile(
            "{\n\t.reg .pred p;\n\t"
            "mbarrier.try_wait.parity.acquire.cta.shared::cta.b64 p, [%1], %2, 0x989680;\n\t"
            "selp.b32 %0, 1, 0, p;\n\t}"
            : "=r"(done) : "r"(mbar), "r"(parity) : "memory");
    } while (!done);
}

__device__ __forceinline__ void stage_issue(uint32_t mbar, uint32_t hs_sm,
                                            const float* srcbase, int t) {
    if (t < 32) {
        if (t == 0)
            asm volatile("mbarrier.arrive.expect_tx.shared.b64 _, [%0], %1;"
                         :: "r"(mbar), "r"((uint32_t)(BT*HID*4)) : "memory");
        __syncwarp();
        uint32_t dst = hs_sm + (uint32_t)t * (HSP * 4);
        const float* src = srcbase + (size_t)t * HID;
        asm volatile(
            "cp.async.bulk.shared::cluster.global.mbarrier::complete_tx::bytes [%0], [%1], %2, [%3];"
            :: "r"(dst), "l"(src), "r"((uint32_t)(HID*4)), "r"(mbar) : "memory");
    }
}

// ---------------- group barrier (release/acquire) ----------------
__device__ __forceinline__ void group_barrier(int g, unsigned target) {
    __syncthreads();
    if (threadIdx.x == 0) {
        __threadfence();
        if (atomicAdd(&g_cnt[g], 1u) == GRP - 1u) {
            atomicExch(&g_cnt[g], 0u);
            __threadfence();
            asm volatile("st.release.gpu.global.u32 [%0], %1;"
                         :: "l"(&g_gen[g]), "r"(target) : "memory");
        } else {
            unsigned cur;
            do {
                asm volatile("ld.acquire.gpu.global.u32 %0, [%1];"
                             : "=r"(cur) : "l"(&g_gen[g]) : "memory");
            } while (cur < target);
        }
    }
    __syncthreads();
}

// ---------------- phase 2: persistent recurrent kernel ----------------
__global__ __launch_bounds__(256, 1) void rnn_kernel(
        const float* __restrict__ Whh, const float* __restrict__ alpha,
        float* __restrict__ out, int write_hn) {
    extern __shared__ char sm[];
    const uint32_t smb  = (uint32_t)__cvta_generic_to_shared(sm);
    ull*   Ws2 = reinterpret_cast<ull*>(sm + OFF_W);
    float* hs  = reinterpret_cast<float*>(sm + OFF_H);
    float* red = reinterpret_cast<float*>(sm + OFF_RED);
    const uint32_t mbar  = smb + OFF_MBAR;
    const uint32_t hs_sm = smb + OFF_H;

    const int t   = threadIdx.x;
    const int jtb = blockIdx.x & 63;       // j tile 0..63
    const int grp = blockIdx.x >> 6;       // batch group 0..1
    const int j0  = jtb * JT;
    const int b0g = grp * BT;

    if (t == 0)
        asm volatile("mbarrier.init.shared.b64 [%0], 1;" :: "r"(mbar) : "memory");
    __syncthreads();

    // kick off staging of h0 while we load W
    stage_issue(mbar, hs_sm, g_h[0] + (size_t)b0g * HID, t);

    // Load W_hh slice: Ws2[kp*WSP + jl] = {W[j0+jl][2kp], W[j0+jl][2kp+1]}
    #pragma unroll
    for (int l = 0; l < 32; l++) {
        int idx = t + l * 256;             // 0..8191
        int jl  = idx >> 9;                // 0..15
        int kp  = idx & 511;               // coalesced along kp
        float2 v = *reinterpret_cast<const float2*>(Whh + (size_t)(j0 + jl) * HID + 2 * kp);
        Ws2[kp * WSP + jl] = pk2(v.x, v.y);
    }

    // thread mapping for compute: warp = k-slice, lane -> (q, jt4)
    const int w   = t >> 5;                // k-slice 0..7 (128 k each)
    const int lan = t & 31;
    const int q   = lan & 7;               // row sub-id: rows {q, q+8, q+16, q+24}
    const int jt4 = lan >> 3;              // j quad 0..3 -> cols 4*jt4..+3

    // epilogue mapping: 2 outputs per thread
    const int re = t >> 3;                 // 0..31 batch row
    const int jp = (t & 7) * 2;            // 0,2,..,14
    const float a0 = alpha[j0 + jp];
    const float a1 = alpha[j0 + jp + 1];
    const size_t hrow_idx = (size_t)(b0g + re) * HID + j0 + jp;

    const ull*   wpB = Ws2 + (size_t)w * 64 * WSP + 4 * jt4;
    const float* hqB = hs + q * HSP + w * 128;

    __syncthreads();    // Ws2 ready

    unsigned step_gen = 0;
    for (int step = 0; step < SEQ; step++) {
        // prefetch xp for this thread's outputs (independent of staging)
        const size_t oidx = (size_t)step * BATCH * HID + hrow_idx;
        float2 xpv = *reinterpret_cast<const float2*>(out + oidx);

        mbar_wait(mbar, step & 1);

        ull acc[4][4];
        #pragma unroll
        for (int m = 0; m < 4; m++)
            #pragma unroll
            for (int j = 0; j < 4; j++) acc[m][j] = 0ull;

        #pragma unroll 8
        for (int kq = 0; kq < 32; kq++) {
            const ull* w0 = wpB + (2 * kq) * WSP;
            const ull* w1 = w0 + WSP;
            ulonglong2 W00 = *reinterpret_cast<const ulonglong2*>(w0);
            ulonglong2 W01 = *reinterpret_cast<const ulonglong2*>(w0 + 2);
            ulonglong2 W10 = *reinterpret_cast<const ulonglong2*>(w1);
            ulonglong2 W11 = *reinterpret_cast<const ulonglong2*>(w1 + 2);
            const float* hk = hqB + 4 * kq;
            #pragma unroll
            for (int m = 0; m < 4; m++) {
                ulonglong2 Hm = *reinterpret_cast<const ulonglong2*>(hk + m * (8 * HSP));
                acc[m][0] = ffma2(Hm.x, W00.x, acc[m][0]);
                acc[m][0] = ffma2(Hm.y, W10.x, acc[m][0]);
                acc[m][1] = ffma2(Hm.x, W00.y, acc[m][1]);
                acc[m][1] = ffma2(Hm.y, W10.y, acc[m][1]);
                acc[m][2] = ffma2(Hm.x, W01.x, acc[m][2]);
                acc[m][2] = ffma2(Hm.y, W11.x, acc[m][2]);
                acc[m][3] = ffma2(Hm.x, W01.y, acc[m][3]);
                acc[m][3] = ffma2(Hm.y, W11.y, acc[m][3]);
            }
        }

        // ---- cross-warp (k-slice) reduction ----
        #pragma unroll
        for (int m = 0; m < 4; m++) {
            float2 p0 = upk(acc[m][0]);
            float2 p1 = upk(acc[m][1]);
            float2 p2 = upk(acc[m][2]);
            float2 p3 = upk(acc[m][3]);
            float4 v = make_float4(p0.x + p0.y, p1.x + p1.y, p2.x + p2.y, p3.x + p3.y);
            *reinterpret_cast<float4*>(red + w * RSP + (q + 8 * m) * 16 + 4 * jt4) = v;
        }
        __syncthreads();

        float s0 = 0.f, s1 = 0.f;
        #pragma unroll
        for (int ww = 0; ww < 8; ww++) {
            float2 rv = *reinterpret_cast<const float2*>(red + ww * RSP + 2 * t);
            s0 += rv.x; s1 += rv.y;
        }

        // ---- epilogue: gate, stores ----
        float hp0 = hs[re * HSP + j0 + jp];
        float hp1 = hs[re * HSP + j0 + jp + 1];
        float ht0 = tanhf(xpv.x + s0);
        float ht1 = tanhf(xpv.y + s1);
        float hn0 = hp0 + a0 * (ht0 - hp0);
        float hn1 = hp1 + a1 * (ht1 - hp1);

        float* hnxt = g_h[(step + 1) & 1];
        *reinterpret_cast<float2*>(hnxt + hrow_idx) = make_float2(hn0, hn1);
        *reinterpret_cast<float2*>(out + oidx)      = make_float2(hn0, hn1);
        if (write_hn && step == SEQ - 1)
            *reinterpret_cast<float2*>(out + (size_t)SBH + hrow_idx) = make_float2(hn0, hn1);

        step_gen++;
        group_barrier(grp, step_gen);

        if (step < SEQ - 1)
            stage_issue(mbar, hs_sm, hnxt + (size_t)b0g * HID, t);
    }
}

// ---------------- launch ----------------
extern "C" void kernel_launch(void* const* d_in, const int* in_sizes, int n_in,
                              void* d_out, int out_size) {
    const float* x     = (const float*)d_in[0];   // [512,64,256]
    const float* W_in  = (const float*)d_in[1];   // [1024,256]
    const float* W_hh  = (const float*)d_in[2];   // [1024,1024]
    const float* bias  = (const float*)d_in[3];   // [1024]
    const float* alpha = (const float*)d_in[4];   // [1024]
    float* out = (float*)d_out;

    cudaFuncSetAttribute(rnn_kernel, cudaFuncAttributeMaxDynamicSharedMemorySize, SMEM_BYTES);

    init_kernel<<<(BATCH*HID + 255) / 256, 256>>>();

    dim3 g1(HID / P1_BN, (SEQ * BATCH) / P1_BM);
    xproj_kernel<<<g1, 256>>>(x, W_in, bias, out);

    int write_hn = (out_size >= SBH + BATCH * HID) ? 1 : 0;
    rnn_kernel<<<NBLK, 256, SMEM_BYTES>>>(W_hh, alpha, out, write_hn);
}